// round 7
// baseline (speedup 1.0000x reference)
#include <cuda_runtime.h>
#include <cuda_bf16.h>
#include <cstdint>

// Problem constants (fixed by the reference)
#define B_    4
#define C_    512
#define H_    64
#define W_    208
#define HID_  512
#define DS_   16
#define NREG_ 4

#define NMEGA_ 148            // persistent blocks (<= 152 SMs on GB300 -> co-resident)
#define NTHR_  1024
#define SG_    32             // reduction subgroups (32 warps)
#define DT_    16             // 16 tiles of 32 columns

#define ROW4_   (W_ / 4)                 // 52
#define TOTAL4_ (B_ * C_ * H_ * ROW4_)   // 6,815,744 float4

// Scratch (device globals; no allocation allowed)
__device__ float    g_tmp  [NREG_ * B_ * HID_];
__device__ float    g_delta[B_ * NREG_ * C_];
__device__ int      g_perm[B_ * W_];
__device__ int      g_reg [B_ * W_];
__device__ unsigned g_ctr [2] = {0u, 0u};   // self-resetting arrival counters
__device__ unsigned g_flag[2] = {0u, 0u};   // monotonic release flags (never reset)

// Grid-wide barrier (all NMEGA_ blocks co-resident). base = flag value sampled
// at kernel entry (before any arrival of this launch -> race-free).
__device__ __forceinline__ void grid_barrier(int k, unsigned base) {
    __syncthreads();
    if (threadIdx.x == 0) {
        __threadfence();                         // make this block's stores cumulative-visible
        unsigned arrived = atomicAdd(&g_ctr[k], 1u);
        if (arrived == NMEGA_ - 1) {
            g_ctr[k] = 0u;                       // safe: next use is next launch
            __threadfence();
            atomicAdd(&g_flag[k], 1u);           // release
        } else {
            while (*(volatile unsigned*)&g_flag[k] == base) { __nanosleep(64); }
        }
        __threadfence();                         // acquire
    }
    __syncthreads();
}

__global__ __launch_bounds__(NTHR_, 1) void mega_kernel(
        const float* __restrict__ image,
        const float* __restrict__ text_feat,
        const int*   __restrict__ text_mask,
        const float* __restrict__ Wv,
        const float* __restrict__ Wo,
        float*       __restrict__ out) {
    __shared__ float s_vec[B_][HID_];            // 8 KB   (tf, then tmp)
    __shared__ float s_red[SG_][B_][32];         // 16 KB
    __shared__ int   s_lab[W_];
    __shared__ __align__(16) int s_perm[B_ * W_];
    __shared__ __align__(16) int s_reg [B_ * W_];
    __shared__ unsigned s_base[2];

    const int tid = threadIdx.x;
    const int blk = blockIdx.x;

    if (tid == 0) { s_base[0] = g_flag[0]; s_base[1] = g_flag[1]; }
    __syncthreads();

    // ===================== Phase 0: stage1 + perm ==========================
    if (blk < 64) {
        // tmp[r,b,d] = sum_h tf[r,b,h] * Wv[r,h,d]
        const int r  = blk / DT_;
        const int dt = blk % DT_;
        const int dl = tid & 31;
        const int hs = tid >> 5;                  // 0..31
        const int d  = dt * 32 + dl;

        for (int i = tid; i < B_ * HID_; i += NTHR_)
            s_vec[i / HID_][i % HID_] = text_feat[(size_t)r * B_ * HID_ + i];
        __syncthreads();

        const float* wv = Wv + (size_t)r * HID_ * HID_ + d;
        float acc[B_] = {0.f, 0.f, 0.f, 0.f};
        #pragma unroll
        for (int h = hs; h < HID_; h += SG_) {    // 16 iterations, fully unrolled
            const float w = wv[(size_t)h * HID_];
            #pragma unroll
            for (int b = 0; b < B_; ++b)
                acc[b] = fmaf(s_vec[b][h], w, acc[b]);
        }
        #pragma unroll
        for (int b = 0; b < B_; ++b) s_red[hs][b][dl] = acc[b];
        __syncthreads();

        if (hs == 0) {
            #pragma unroll
            for (int b = 0; b < B_; ++b) {
                float s = 0.f;
                #pragma unroll
                for (int g = 0; g < SG_; ++g) s += s_red[g][b][dl];
                g_tmp[((size_t)r * B_ + b) * HID_ + d] = s;
            }
        }
    } else if (blk < 68) {
        // stable counting-sort perm (parallel rank), one block per batch
        const int b = blk - 64;
        const size_t mask_batch_stride = (size_t)(H_ * DS_) * (W_ * DS_);
        if (tid < W_)
            s_lab[tid] = text_mask[b * mask_batch_stride + (size_t)tid * DS_];
        __syncthreads();
        if (tid < W_) {
            const int lab = s_lab[tid];
            int pos = 0;
            #pragma unroll 8
            for (int w2 = 0; w2 < W_; ++w2) {
                const int l2 = s_lab[w2];
                pos += (l2 < lab) || (l2 == lab && w2 < tid);
            }
            g_perm[b * W_ + pos] = tid;
            g_reg [b * W_ + pos] = lab - 1;
        }
    }

    grid_barrier(0, s_base[0]);

    // ===================== Phase 1: stage2 =================================
    if (blk < 64) {
        // delta[b,r,c] = sum_d tmp[r,b,d] * Wo[r,d,c]
        const int r  = blk / DT_;
        const int ct = blk % DT_;
        const int cl = tid & 31;
        const int ds = tid >> 5;
        const int c  = ct * 32 + cl;

        for (int i = tid; i < B_ * HID_; i += NTHR_)
            s_vec[i / HID_][i % HID_] = __ldcg(&g_tmp[(size_t)r * B_ * HID_ + i]);
        __syncthreads();

        const float* wo = Wo + (size_t)r * HID_ * C_ + c;
        float acc[B_] = {0.f, 0.f, 0.f, 0.f};
        #pragma unroll
        for (int d = ds; d < HID_; d += SG_) {
            const float w = wo[(size_t)d * C_];
            #pragma unroll
            for (int b = 0; b < B_; ++b)
                acc[b] = fmaf(s_vec[b][d], w, acc[b]);
        }
        #pragma unroll
        for (int b = 0; b < B_; ++b) s_red[ds][b][cl] = acc[b];
        __syncthreads();

        if (ds == 0) {
            #pragma unroll
            for (int b = 0; b < B_; ++b) {
                float s = 0.f;
                #pragma unroll
                for (int g = 0; g < SG_; ++g) s += s_red[g][b][cl];
                g_delta[((size_t)b * NREG_ + r) * C_ + c] = s;
            }
        }
    }

    grid_barrier(1, s_base[1]);

    // ===================== Phase 2: gather (all blocks) ====================
    // stage the LUTs (all batches) into smem, L1-bypassing for coherence
    for (int i = tid; i < B_ * W_; i += NTHR_) {
        s_perm[i] = __ldcg(&g_perm[i]);
        s_reg [i] = __ldcg(&g_reg [i]);
    }
    __syncthreads();

    for (int idx = blk * NTHR_ + tid; idx < TOTAL4_; idx += NMEGA_ * NTHR_) {
        const int w4  = idx % ROW4_;
        const int row = idx / ROW4_;              // linear over (b, c, h)
        const int b   = row >> 15;                // / (C_*H_) = 32768
        const int c   = (row >> 6) & (C_ - 1);
        const int w   = w4 * 4;

        const int4 s4 = *reinterpret_cast<const int4*>(&s_perm[b * W_ + w]);
        const int4 r4 = *reinterpret_cast<const int4*>(&s_reg [b * W_ + w]);

        const float* imrow = image + (size_t)row * W_;
        const float* drow  = g_delta + (size_t)b * NREG_ * C_ + c;

        float4 o;
        o.x = __ldg(imrow + s4.x) + __ldcg(drow + r4.x * C_);
        o.y = __ldg(imrow + s4.y) + __ldcg(drow + r4.y * C_);
        o.z = __ldg(imrow + s4.z) + __ldcg(drow + r4.z * C_);
        o.w = __ldg(imrow + s4.w) + __ldcg(drow + r4.w * C_);

        reinterpret_cast<float4*>(out)[idx] = o;
    }
}

// ---------------------------------------------------------------------------
// Launch. Input order (metadata): image_feature f32, text_feat f32,
// text_mask i32, Wq f32 (unused), Wk f32 (unused), Wv f32, Wo f32.
// ---------------------------------------------------------------------------
extern "C" void kernel_launch(void* const* d_in, const int* in_sizes, int n_in,
                              void* d_out, int out_size) {
    const float* image     = (const float*)d_in[0];
    const float* text_feat = (const float*)d_in[1];
    const int*   text_mask = (const int*)  d_in[2];
    const float* Wv        = (const float*)d_in[5];
    const float* Wo        = (const float*)d_in[6];
    float* out = (float*)d_out;

    mega_kernel<<<NMEGA_, NTHR_>>>(image, text_feat, text_mask, Wv, Wo, out);
}

// round 8
// speedup vs baseline: 1.4933x; 1.4933x over previous
#include <cuda_runtime.h>
#include <cuda_bf16.h>
#include <cstdint>

// Problem constants (fixed by the reference)
#define B_    4
#define C_    512
#define H_    64
#define W_    208
#define HID_  512
#define DS_   16
#define NREG_ 4

// Stage geometry: 4 regions x 8 column-tiles of 64 (float4 per thread)
#define DTIL_  8
#define COLS_  64                    // columns per tile (16 lanes x float4)
#define NSUB_  32                    // h-subgroups per block (512 thr / 16 lanes)
#define NBLKS_ (NREG_ * DTIL_)       // 32 blocks per stage

// Fused-kernel block roles
#define NBLK1_ NBLKS_                          // stage1 blocks [0, 32)
#define NBLKP_ B_                              // perm blocks   [32, 36)
#define NBLK2_ NBLKS_                          // stage2 blocks [36, 68)
#define NBLKF_ (NBLK1_ + NBLKP_ + NBLK2_)      // 68 <= 148 SMs -> co-resident

// Scratch (device globals; no allocation allowed)
__device__ float g_tmp  [NREG_ * B_ * HID_];  // tmp[r, b, d]
__device__ float g_delta[B_ * NREG_ * C_];    // delta[b, r, c]
__device__ int   g_perm[B_ * W_];             // output col w -> source col
__device__ int   g_reg [B_ * W_];             // output col w -> region id (0..3)
__device__ int   g_done = 0;                  // stage1 arrival counter

// Shared GEMV-stage body: out[(sel)*HID + coltile] = sum_k vec[b][k] * Wmat[k][col]
// Wmat is HID_ x NC row-major. 512 threads: lane = tid&15 (4 cols via float4),
// hs = tid>>4 (0..31) strides k. High MLP: unroll-8 float4 loads = 32 lines
// in flight per thread.
template<int NC>
__device__ __forceinline__ void gemv_stage(
        const float* __restrict__ Wmat,       // + r offset applied by caller
        const float (*s_vec)[HID_],           // [B_][HID_] in smem
        float (*s_red)[B_][COLS_],            // [NSUB_][B_][COLS_]
        float* __restrict__ out_base,         // out for (b): out_base + b_stride*b + col
        size_t b_stride,
        int coltile, int tid) {
    const int lane = tid & 15;
    const int hs   = tid >> 4;                // 0..31
    const int col  = coltile * COLS_ + lane * 4;

    const float* wp = Wmat + col;
    float4 acc[B_];
    #pragma unroll
    for (int b = 0; b < B_; ++b) acc[b] = make_float4(0.f, 0.f, 0.f, 0.f);

    #pragma unroll 8
    for (int k = hs; k < HID_; k += NSUB_) {
        const float4 w = *reinterpret_cast<const float4*>(wp + (size_t)k * NC);
        #pragma unroll
        for (int b = 0; b < B_; ++b) {
            const float v = s_vec[b][k];
            acc[b].x = fmaf(v, w.x, acc[b].x);
            acc[b].y = fmaf(v, w.y, acc[b].y);
            acc[b].z = fmaf(v, w.z, acc[b].z);
            acc[b].w = fmaf(v, w.w, acc[b].w);
        }
    }

    #pragma unroll
    for (int b = 0; b < B_; ++b) {
        s_red[hs][b][lane * 4 + 0] = acc[b].x;
        s_red[hs][b][lane * 4 + 1] = acc[b].y;
        s_red[hs][b][lane * 4 + 2] = acc[b].z;
        s_red[hs][b][lane * 4 + 3] = acc[b].w;
    }
    __syncthreads();

    // 256 threads reduce: b = tid>>6, c = tid&63
    if (tid < B_ * COLS_) {
        const int b = tid >> 6;
        const int c = tid & 63;
        float s = 0.f;
        #pragma unroll
        for (int g = 0; g < NSUB_; ++g) s += s_red[g][b][c];
        out_base[b_stride * b + coltile * COLS_ + c] = s;
    }
}

// ---------------------------------------------------------------------------
// Fused setup kernel, 68 blocks x 512 threads (co-resident in one wave):
//   [0,32):  stage1  tmp[r,b,d] = sum_h tf[r,b,h] * Wv[r,h,d]
//   [32,36): perm    stable counting-sort rank per batch
//   [36,68): stage2  delta[b,r,c] = sum_d tmp[r,b,d] * Wo[r,d,c]
//            (spins on g_done until all 32 stage1 blocks released)
// g_done is reset by the gather kernel (stream order => visible next replay).
// ---------------------------------------------------------------------------
__global__ __launch_bounds__(512) void setup_fused(
        const float* __restrict__ text_feat,
        const float* __restrict__ Wv,
        const float* __restrict__ Wo,
        const int*   __restrict__ text_mask) {
    __shared__ float s_vec[B_][HID_];               // 8 KB
    __shared__ float s_red[NSUB_][B_][COLS_];       // 32 KB
    __shared__ int   s_lab[W_];

    const int blk = blockIdx.x;
    const int tid = threadIdx.x;

    if (blk < NBLK1_) {
        // ---------------- stage 1 ----------------
        const int r  = blk / DTIL_;
        const int dt = blk % DTIL_;

        for (int i = tid; i < B_ * HID_; i += 512)
            s_vec[i / HID_][i % HID_] = text_feat[(size_t)r * B_ * HID_ + i];
        __syncthreads();

        gemv_stage<HID_>(Wv + (size_t)r * HID_ * HID_, s_vec, s_red,
                         g_tmp + (size_t)r * B_ * HID_, HID_, dt, tid);
        __syncthreads();
        __threadfence();
        if (tid == 0) atomicAdd(&g_done, 1);

    } else if (blk < NBLK1_ + NBLKP_) {
        // ---------------- perm (stable counting sort via parallel rank) ----
        const int b = blk - NBLK1_;
        const size_t mask_batch_stride = (size_t)(H_ * DS_) * (W_ * DS_);
        if (tid < W_)
            s_lab[tid] = text_mask[b * mask_batch_stride + (size_t)tid * DS_];
        __syncthreads();
        if (tid < W_) {
            const int lab = s_lab[tid];
            int pos = 0;
            #pragma unroll 8
            for (int w2 = 0; w2 < W_; ++w2) {
                const int l2 = s_lab[w2];
                pos += (l2 < lab) || (l2 == lab && w2 < tid);
            }
            g_perm[b * W_ + pos] = tid;
            g_reg [b * W_ + pos] = lab - 1;
        }

    } else {
        // ---------------- stage 2 ----------------
        const int id = blk - NBLK1_ - NBLKP_;
        const int r  = id / DTIL_;
        const int ct = id % DTIL_;

        if (tid == 0) {
            while (*((volatile int*)&g_done) < NBLK1_) { }
        }
        __syncthreads();
        __threadfence();

        for (int i = tid; i < B_ * HID_; i += 512)
            s_vec[i / HID_][i % HID_] = __ldcg(&g_tmp[(size_t)r * B_ * HID_ + i]);
        __syncthreads();

        // delta[b,r,c]: out index (b*NREG + r)*C + c  -> base g_delta + r*C, b-stride NREG*C
        gemv_stage<C_>(Wo + (size_t)r * HID_ * C_, s_vec, s_red,
                       g_delta + (size_t)r * C_, (size_t)NREG_ * C_, ct, tid);
    }
}

// ---------------------------------------------------------------------------
// Gather (R3 winner): out[b,c,h,w] = image[b,c,h, perm[b,w]] + delta[b, reg[b,w], c]
// Exact grid over float4 outputs. Writes coalesced; reads permuted within each
// 832B row (L1 absorbs); LUTs L2-resident and ~warp-uniform.
// ---------------------------------------------------------------------------
#define ROW4_ (W_ / 4)                 // 52
#define TOTAL4_ (B_ * C_ * H_ * ROW4_)

__global__ __launch_bounds__(256) void gather_add_kernel(
        const float* __restrict__ image, float* __restrict__ out) {
    int idx = blockIdx.x * blockDim.x + threadIdx.x;
    if (idx >= TOTAL4_) return;

    // reset setup's arrival counter for the next graph replay
    if (idx == 0) g_done = 0;

    const int w4  = idx % ROW4_;
    const int row = idx / ROW4_;       // linear over (b, c, h)
    const int c   = (row >> 6) & (C_ - 1);
    const int b   = row >> 15;
    const int w   = w4 * 4;

    const int4 s4 = *reinterpret_cast<const int4*>(&g_perm[b * W_ + w]);
    const int4 r4 = *reinterpret_cast<const int4*>(&g_reg [b * W_ + w]);

    const float* imrow = image + (size_t)row * W_;
    const float* drow  = &g_delta[b * NREG_ * C_ + c];  // + r*C_

    float4 o;
    o.x = __ldg(imrow + s4.x) + drow[r4.x * C_];
    o.y = __ldg(imrow + s4.y) + drow[r4.y * C_];
    o.z = __ldg(imrow + s4.z) + drow[r4.z * C_];
    o.w = __ldg(imrow + s4.w) + drow[r4.w * C_];

    reinterpret_cast<float4*>(out)[idx] = o;
}

// ---------------------------------------------------------------------------
// Launch. Input order (metadata): image_feature f32, text_feat f32,
// text_mask i32, Wq f32 (unused), Wk f32 (unused), Wv f32, Wo f32.
// ---------------------------------------------------------------------------
extern "C" void kernel_launch(void* const* d_in, const int* in_sizes, int n_in,
                              void* d_out, int out_size) {
    const float* image     = (const float*)d_in[0];
    const float* text_feat = (const float*)d_in[1];
    const int*   text_mask = (const int*)  d_in[2];
    const float* Wv        = (const float*)d_in[5];
    const float* Wo        = (const float*)d_in[6];
    float* out = (float*)d_out;

    setup_fused<<<NBLKF_, 512>>>(text_feat, Wv, Wo, text_mask);

    const int threads = 256;
    const int blocks = (TOTAL4_ + threads - 1) / threads;
    gather_add_kernel<<<blocks, threads>>>(image, out);
}